// round 1
// baseline (speedup 1.0000x reference)
#include <cuda_runtime.h>
#include <cuda_bf16.h>
#include <cstddef>

// ---------------------------------------------------------------------------
// Problem constants (shapes are static for this problem instance)
// ---------------------------------------------------------------------------
#define B_SZ   2
#define S_SZ   4096      // 64 x 64 tokens
#define HID    2048
#define NH     32
#define HD     64
#define NHD    2048      // NH*HD
#define M_ROWS (B_SZ * S_SZ)       // 8192
#define NT     32        // query tiles (8 x 4 tile grid)
#define TN_TOK 128       // tokens per tile (8 x 16)
#define NKV    4         // kv tiles per query tile (2 x 2 window)
#define SCALE_F 0.125f   // 1/sqrt(64)

// ---------------------------------------------------------------------------
// Scratch (device globals: allocation-free rule)
// ---------------------------------------------------------------------------
__device__ float g_q[M_ROWS * NHD];
__device__ float g_k[M_ROWS * NHD];
__device__ float g_v[M_ROWS * NHD];
__device__ float g_att[M_ROWS * NHD];

// ---------------------------------------------------------------------------
// SGEMM body: C[M,N] = A[M,K] @ B[K,N], all row-major, fp32.
// 128x128 block tile, BK=8, 256 threads, 8x8 per-thread microtile with a
// 4+4 split (rows {r..r+3, r+64..r+67}) for conflict-free LDS.128 fragments.
// Double-buffered smem. M%128==0, N%128==0, K%8==0 assumed.
// ---------------------------------------------------------------------------
__device__ __forceinline__ void gemm_body(
    const float* __restrict__ A, const float* __restrict__ B,
    float* __restrict__ C, int M, int N, int K)
{
    __shared__ float As[2][8][128];
    __shared__ float Bs[2][8][128];

    const int tid = threadIdx.x;
    const int bx = blockIdx.x, by = blockIdx.y;

    const int arow = tid >> 1, acol = (tid & 1) * 4;
    const int brow = tid >> 5, bcol = (tid & 31) * 4;
    const int tr4  = (tid >> 4) * 4, tc4 = (tid & 15) * 4;

    const float* Ag = A + (size_t)(by * 128 + arow) * K + acol;
    const float* Bg = B + (size_t)brow * N + bx * 128 + bcol;

    float acc[8][8];
#pragma unroll
    for (int i = 0; i < 8; i++)
#pragma unroll
        for (int j = 0; j < 8; j++) acc[i][j] = 0.f;

    float4 a4 = *(const float4*)(Ag);
    float4 b4 = *(const float4*)(Bg);
    As[0][acol + 0][arow] = a4.x;
    As[0][acol + 1][arow] = a4.y;
    As[0][acol + 2][arow] = a4.z;
    As[0][acol + 3][arow] = a4.w;
    *(float4*)&Bs[0][brow][bcol] = b4;
    __syncthreads();

    const int nk = K >> 3;
    for (int t = 0; t < nk; ++t) {
        const int cur = t & 1;
        if (t + 1 < nk) {
            a4 = *(const float4*)(Ag + (t + 1) * 8);
            b4 = *(const float4*)(Bg + (size_t)(t + 1) * 8 * N);
        }
#pragma unroll
        for (int k = 0; k < 8; ++k) {
            float ar[8], br[8];
            *(float4*)(ar)     = *(const float4*)&As[cur][k][tr4];
            *(float4*)(ar + 4) = *(const float4*)&As[cur][k][tr4 + 64];
            *(float4*)(br)     = *(const float4*)&Bs[cur][k][tc4];
            *(float4*)(br + 4) = *(const float4*)&Bs[cur][k][tc4 + 64];
#pragma unroll
            for (int i = 0; i < 8; i++)
#pragma unroll
                for (int j = 0; j < 8; j++)
                    acc[i][j] = fmaf(ar[i], br[j], acc[i][j]);
        }
        if (t + 1 < nk) {
            const int nxt = cur ^ 1;
            As[nxt][acol + 0][arow] = a4.x;
            As[nxt][acol + 1][arow] = a4.y;
            As[nxt][acol + 2][arow] = a4.z;
            As[nxt][acol + 3][arow] = a4.w;
            *(float4*)&Bs[nxt][brow][bcol] = b4;
        }
        __syncthreads();
    }

#pragma unroll
    for (int i = 0; i < 8; i++) {
        const int row = by * 128 + ((i < 4) ? (tr4 + i) : (64 + tr4 + (i - 4)));
        float* Cr = C + (size_t)row * N + bx * 128;
        *(float4*)(Cr + tc4)      = make_float4(acc[i][0], acc[i][1], acc[i][2], acc[i][3]);
        *(float4*)(Cr + tc4 + 64) = make_float4(acc[i][4], acc[i][5], acc[i][6], acc[i][7]);
    }
}

// Fused QKV: blockIdx.z selects weight/output, sharing A (hidden states stay
// hot in L2 across the 3 sub-GEMMs of a wave).
__global__ __launch_bounds__(256, 2) void qkv_kernel(
    const float* __restrict__ A,
    const float* __restrict__ W0, const float* __restrict__ W1, const float* __restrict__ W2,
    float* __restrict__ C0, float* __restrict__ C1, float* __restrict__ C2)
{
    const float* W = (blockIdx.z == 0) ? W0 : (blockIdx.z == 1) ? W1 : W2;
    float*       C = (blockIdx.z == 0) ? C0 : (blockIdx.z == 1) ? C1 : C2;
    gemm_body(A, W, C, M_ROWS, NHD, HID);
}

__global__ __launch_bounds__(256, 2) void gemm_kernel(
    const float* __restrict__ A, const float* __restrict__ B, float* __restrict__ C,
    int M, int N, int K)
{
    gemm_body(A, B, C, M, N, K);
}

// ---------------------------------------------------------------------------
// Block-sparse tiled attention.
// Grid: (tile t=0..31, head h=0..31, batch b=0..1). 256 threads.
// Thread (p = tid>>7, j = tid&127): owns query row j; p splits keys in QK and
// the head dim in PV. Flash-style online softmax over the 4 kv tiles.
// ---------------------------------------------------------------------------
#define ATT_SMEM_FLOATS (128 * 64 * 2 + 128 * 129 + 256)
#define ATT_SMEM_BYTES  (ATT_SMEM_FLOATS * 4)

__device__ __forceinline__ int token_of(int tile, int jj)
{
    // s = (tile>>2)*512 + (jj>>4)*64 + (tile&3)*16 + (jj&15)
    return ((tile >> 2) << 9) + ((jj >> 4) << 6) + ((tile & 3) << 4) + (jj & 15);
}

__global__ __launch_bounds__(256) void attn_kernel(
    const float* __restrict__ Q, const float* __restrict__ Kb,
    const float* __restrict__ Vb, float* __restrict__ O)
{
    extern __shared__ float sm[];
    float* Ks = sm;                       // [128][64]
    float* Vs = sm + 128 * 64;            // [128][64]
    float* Ss = sm + 2 * 128 * 64;        // [128][129] padded scores
    float* Rm = Ss + 128 * 129;           // [2][128] per-half row maxima

    const int t = blockIdx.x, h = blockIdx.y, b = blockIdx.z;
    const int tid = threadIdx.x;
    const int p = tid >> 7, j = tid & 127;

    // kv tile window (static sliding window, clamped to the 8x4 tile grid)
    const int tr = t >> 2, tc = t & 3;
    const int cr = min(max(tr, 1), 7);
    const int cc = min(max(tc, 1), 3);
    int kts[NKV];
    kts[0] = (cr - 1) * 4 + (cc - 1);
    kts[1] = (cr - 1) * 4 + cc;
    kts[2] = cr * 4 + (cc - 1);
    kts[3] = cr * 4 + cc;

    const size_t base = (size_t)b * S_SZ * NHD + (size_t)h * HD;

    // Load this thread's query row into registers (duplicated across p).
    const int qs = token_of(t, j);
    const float* qrow = Q + base + (size_t)qs * NHD;
    float4 qv[16];
#pragma unroll
    for (int i = 0; i < 16; i++) qv[i] = *(const float4*)(qrow + i * 4);

    float m = -1e30f, l = 0.f;
    float o[32];
#pragma unroll
    for (int d = 0; d < 32; d++) o[d] = 0.f;

    for (int w = 0; w < NKV; ++w) {
        const int kt = kts[w];
        __syncthreads();   // previous tile's Ss/Vs consumption complete
        // Cooperative K/V tile load: 128 rows x 16 float4 each.
        for (int idx = tid; idx < 128 * 16; idx += 256) {
            const int row = idx >> 4, c4 = (idx & 15) * 4;
            const int ks = token_of(kt, row);
            const size_t off = base + (size_t)ks * NHD + c4;
            *(float4*)&Ks[row * 64 + c4] = *(const float4*)(Kb + off);
            *(float4*)&Vs[row * 64 + c4] = *(const float4*)(Vb + off);
        }
        __syncthreads();

        // QK: thread (j,p) scores keys [p*64, p*64+64). K rows broadcast
        // across the warp (all lanes share kk,p) -> conflict-free.
        float tmax = -1e30f;
        for (int kk = 0; kk < 64; ++kk) {
            const int key = p * 64 + kk;
            const float* kr = &Ks[key * 64];
            float s0 = 0.f, s1 = 0.f, s2 = 0.f, s3 = 0.f;
#pragma unroll
            for (int i = 0; i < 16; i++) {
                const float4 k4 = *(const float4*)(kr + i * 4);
                s0 = fmaf(qv[i].x, k4.x, s0);
                s1 = fmaf(qv[i].y, k4.y, s1);
                s2 = fmaf(qv[i].z, k4.z, s2);
                s3 = fmaf(qv[i].w, k4.w, s3);
            }
            float s = ((s0 + s1) + (s2 + s3)) * SCALE_F;
            Ss[j * 129 + key] = s;       // stride 129: conflict-free columns
            tmax = fmaxf(tmax, s);
        }
        Rm[p * 128 + j] = tmax;
        __syncthreads();

        // Online softmax update (both p threads compute identical m/l).
        const float mt = fmaxf(Rm[j], Rm[128 + j]);
        const float mnew = fmaxf(m, mt);
        const float alpha = __expf(m - mnew);   // exp(-inf)=0 on first tile
        m = mnew;
        l *= alpha;
#pragma unroll
        for (int d = 0; d < 32; d++) o[d] *= alpha;

        // PV: thread (j,p) accumulates dims [p*32, p*32+32) over all 128 keys.
        float lsum = 0.f;
        const float* vbp = &Vs[p * 32];
        for (int k2 = 0; k2 < 128; ++k2) {
            const float e = __expf(Ss[j * 129 + k2] - m);
            lsum += e;
            const float* vr = vbp + k2 * 64;
#pragma unroll
            for (int d4 = 0; d4 < 8; d4++) {
                const float4 v4 = *(const float4*)(vr + d4 * 4);
                o[d4 * 4 + 0] = fmaf(e, v4.x, o[d4 * 4 + 0]);
                o[d4 * 4 + 1] = fmaf(e, v4.y, o[d4 * 4 + 1]);
                o[d4 * 4 + 2] = fmaf(e, v4.z, o[d4 * 4 + 2]);
                o[d4 * 4 + 3] = fmaf(e, v4.w, o[d4 * 4 + 3]);
            }
        }
        l += lsum;
    }

    const float inv = 1.f / l;
    float* orow = O + base + (size_t)qs * NHD + p * 32;
#pragma unroll
    for (int d4 = 0; d4 < 8; d4++) {
        *(float4*)(orow + d4 * 4) = make_float4(
            o[d4 * 4 + 0] * inv, o[d4 * 4 + 1] * inv,
            o[d4 * 4 + 2] * inv, o[d4 * 4 + 3] * inv);
    }
}

// ---------------------------------------------------------------------------
// Launch
// ---------------------------------------------------------------------------
extern "C" void kernel_launch(void* const* d_in, const int* in_sizes, int n_in,
                              void* d_out, int out_size)
{
    const float* hs = (const float*)d_in[0];
    const float* Wq = (const float*)d_in[1];
    const float* Wk = (const float*)d_in[2];
    const float* Wv = (const float*)d_in[3];
    const float* Wo = (const float*)d_in[4];
    float* out = (float*)d_out;

    float *q, *k, *v, *att;
    cudaGetSymbolAddress((void**)&q,   g_q);
    cudaGetSymbolAddress((void**)&k,   g_k);
    cudaGetSymbolAddress((void**)&v,   g_v);
    cudaGetSymbolAddress((void**)&att, g_att);

    // >48KB dynamic smem for the attention kernel (idempotent, capture-legal).
    cudaFuncSetAttribute(attn_kernel, cudaFuncAttributeMaxDynamicSharedMemorySize,
                         ATT_SMEM_BYTES);

    const dim3 tb(256);

    // 1) Fused QKV projections: [8192,2048] @ [2048,2048] x3
    qkv_kernel<<<dim3(NHD / 128, M_ROWS / 128, 3), tb>>>(hs, Wq, Wk, Wv, q, k, v);

    // 2) Block-sparse tiled attention
    attn_kernel<<<dim3(NT, NH, B_SZ), tb, ATT_SMEM_BYTES>>>(q, k, v, att);

    // 3) Output projection: [8192,2048] @ [2048,2048]
    gemm_kernel<<<dim3(HID / 128, M_ROWS / 128), tb>>>(att, Wo, out, M_ROWS, HID, NHD);
}